// round 10
// baseline (speedup 1.0000x reference)
#include <cuda_runtime.h>
#include <cuda_bf16.h>
#include <math.h>

// Problem constants
#define NB 2
#define EE 16
#define CC 16
#define VV (64*128*128)              // 1,048,576 voxels per batch

#define CHUNK1 2048
#define P1_GX (VV / CHUNK1)          // 512 chunks per batch
#define P1_ITERS (CHUNK1 / 128)      // 16 float4-iterations per lane

#define P2_THREADS 256
#define P2_GX (VV / (P2_THREADS*4))  // 1024 blocks per batch
#define P2_TOTAL (P2_GX * NB)        // ticket target across BOTH pass2 launches

#define DELTA_VAR 0.5f
#define DELTA_DIST 1.5f

// Scratch (device globals; zero-initialized at load; the fused finalize
// re-zeros them after consuming, so every call sees zeros -> deterministic).
__device__ float g_sums[NB][CC][EE];
__device__ float g_counts[NB][CC];
__device__ float g_var[NB][CC];
__device__ unsigned int g_ticket;

// ---------------------------------------------------------------------------
// Pass 1: per-cluster sums + counts (smem slot-split, high-MLP), one batch.
// 8 warps; warp w owns planes w and w+8 as two DISJOINT per-lane-column
// accumulator arrays (bank==lane, conflict-free). Labels LDG'd directly as
// int4. Depth-2 software pipeline -> 6 LDG.128 in flight per warp.
// smem: 16KB A + 16KB B + 2KB C = 34KB static.
// Batch passed as arg so batches run SEQUENTIALLY: after this kernel, the
// batch's x (67MB) + t (4MB) are L2-resident (71MB < 126MB L2) for pass 2.
// ---------------------------------------------------------------------------
__global__ __launch_bounds__(256)
void pass1_kernel(const float* __restrict__ x, const int* __restrict__ t,
                  const int n) {
    __shared__ float accA[8][CC * 32];   // 16 KB  (plane w)
    __shared__ float accB[8][CC * 32];   // 16 KB  (plane w+8)
    __shared__ float accC[CC * 32];      // 2 KB   (counts, warp 0)

    const int base = blockIdx.x * CHUNK1;
    const int tid  = threadIdx.x;
    const int w    = tid >> 5;
    const int lane = tid & 31;

    for (int i = tid; i < 8 * CC * 32; i += 256) {
        (&accA[0][0])[i] = 0.0f;
        (&accB[0][0])[i] = 0.0f;
    }
    for (int i = tid; i < CC * 32; i += 256) accC[i] = 0.0f;
    __syncthreads();

    float* A = accA[w];
    float* B = accB[w];
    const float* xpA = x + ((size_t)n * EE + w    ) * VV + base;
    const float* xpB = x + ((size_t)n * EE + w + 8) * VV + base;
    const int*   tp  = t + (size_t)n * VV + base;

    // depth-2 pipeline: slots 0/1, 6 LDG.128 outstanding
    int i = lane * 4;
    float4 va0 = *(const float4*)(xpA + i);
    float4 vb0 = *(const float4*)(xpB + i);
    int4   lb0 = *(const int4*)(tp + i);
    float4 va1 = *(const float4*)(xpA + i + 128);
    float4 vb1 = *(const float4*)(xpB + i + 128);
    int4   lb1 = *(const int4*)(tp + i + 128);

    if (w == 0) {
        #pragma unroll
        for (int it = 0; it < P1_ITERS; it++) {
            float4 va = (it & 1) ? va1 : va0;
            float4 vb = (it & 1) ? vb1 : vb0;
            int4   lb = (it & 1) ? lb1 : lb0;
            if (it + 2 < P1_ITERS) {
                const int off = i + 256;
                if (it & 1) {
                    va1 = *(const float4*)(xpA + off);
                    vb1 = *(const float4*)(xpB + off);
                    lb1 = *(const int4*)(tp + off);
                } else {
                    va0 = *(const float4*)(xpA + off);
                    vb0 = *(const float4*)(xpB + off);
                    lb0 = *(const int4*)(tp + off);
                }
            }
            A[lb.x * 32 + lane] += va.x;  B[lb.x * 32 + lane] += vb.x;  accC[lb.x * 32 + lane] += 1.0f;
            A[lb.y * 32 + lane] += va.y;  B[lb.y * 32 + lane] += vb.y;  accC[lb.y * 32 + lane] += 1.0f;
            A[lb.z * 32 + lane] += va.z;  B[lb.z * 32 + lane] += vb.z;  accC[lb.z * 32 + lane] += 1.0f;
            A[lb.w * 32 + lane] += va.w;  B[lb.w * 32 + lane] += vb.w;  accC[lb.w * 32 + lane] += 1.0f;
            i += 128;
        }
    } else {
        #pragma unroll
        for (int it = 0; it < P1_ITERS; it++) {
            float4 va = (it & 1) ? va1 : va0;
            float4 vb = (it & 1) ? vb1 : vb0;
            int4   lb = (it & 1) ? lb1 : lb0;
            if (it + 2 < P1_ITERS) {
                const int off = i + 256;
                if (it & 1) {
                    va1 = *(const float4*)(xpA + off);
                    vb1 = *(const float4*)(xpB + off);
                    lb1 = *(const int4*)(tp + off);
                } else {
                    va0 = *(const float4*)(xpA + off);
                    vb0 = *(const float4*)(xpB + off);
                    lb0 = *(const int4*)(tp + off);
                }
            }
            A[lb.x * 32 + lane] += va.x;  B[lb.x * 32 + lane] += vb.x;
            A[lb.y * 32 + lane] += va.y;  B[lb.y * 32 + lane] += vb.y;
            A[lb.z * 32 + lane] += va.z;  B[lb.z * 32 + lane] += vb.z;
            A[lb.w * 32 + lane] += va.w;  B[lb.w * 32 + lane] += vb.w;
            i += 128;
        }
    }
    __syncwarp();

    #pragma unroll
    for (int c = 0; c < CC; c++) {
        float sA = A[c * 32 + lane];
        float sB = B[c * 32 + lane];
        #pragma unroll
        for (int o = 16; o > 0; o >>= 1) {
            sA += __shfl_xor_sync(0xffffffffu, sA, o);
            sB += __shfl_xor_sync(0xffffffffu, sB, o);
        }
        if (lane == 0) {
            atomicAdd(&g_sums[n][c][w],     sA);
            atomicAdd(&g_sums[n][c][w + 8], sB);
        }
        if (w == 0) {
            float sC = accC[c * 32 + lane];
            #pragma unroll
            for (int o = 16; o > 0; o >>= 1) sC += __shfl_xor_sync(0xffffffffu, sC, o);
            if (lane == 0) atomicAdd(&g_counts[n][c], sC);
        }
    }
}

// ---------------------------------------------------------------------------
// Pass 2: variance term for ONE batch (launched right after that batch's
// pass 1, so x/t should be L2-resident). Finalize FUSED into the globally
// last pass2 block via ticket across both launches.
// One float4 (4 voxels) per thread; 8 LDG.128 in flight per plane batch.
// ---------------------------------------------------------------------------
__global__ __launch_bounds__(P2_THREADS)
void pass2_kernel(const float* __restrict__ x, const int* __restrict__ t,
                  float* __restrict__ out, const int n) {
    __shared__ float means_s[CC * 20];      // padded stride 20
    __shared__ float vacc[8][CC * 32];      // 16 KB (8 warps)
    __shared__ float wpart[8][CC];
    __shared__ unsigned int s_ticket;

    const int tid  = threadIdx.x;
    const int w    = tid >> 5;
    const int lane = tid & 31;

    if (tid < CC * EE) {
        int c = tid >> 4, e = tid & 15;
        means_s[c * 20 + e] = g_sums[n][c][e] / g_counts[n][c];
    }
    for (int i = tid; i < 8 * CC * 32; i += P2_THREADS) (&vacc[0][0])[i] = 0.0f;
    __syncthreads();

    // reversed bijective index -> 4 consecutive voxels, warp stays contiguous
    const int idx = (P2_GX * P2_THREADS - 1) - (blockIdx.x * P2_THREADS + tid);
    const int v   = idx * 4;

    const float* xb = x + (size_t)n * EE * VV;
    const int4 lb = *(const int4*)(t + (size_t)n * VV + v);

    float ss0 = 0.0f, ss1 = 0.0f, ss2 = 0.0f, ss3 = 0.0f;
    #pragma unroll
    for (int eo = 0; eo < EE; eo += 8) {
        float4 xv[8];
        #pragma unroll
        for (int e = 0; e < 8; e++)
            xv[e] = *(const float4*)(xb + (size_t)(eo + e) * VV + v);
        #pragma unroll
        for (int e = 0; e < 8; e++) {
            const int ee = eo + e;
            float d;
            d = xv[e].x - means_s[lb.x * 20 + ee]; ss0 = fmaf(d, d, ss0);
            d = xv[e].y - means_s[lb.y * 20 + ee]; ss1 = fmaf(d, d, ss1);
            d = xv[e].z - means_s[lb.z * 20 + ee]; ss2 = fmaf(d, d, ss2);
            d = xv[e].w - means_s[lb.w * 20 + ee]; ss3 = fmaf(d, d, ss3);
        }
    }

    float* myv = vacc[w];
    float h;
    h = fmaxf(sqrtf(ss0) - DELTA_VAR, 0.0f); myv[lb.x * 32 + lane] += h * h;
    h = fmaxf(sqrtf(ss1) - DELTA_VAR, 0.0f); myv[lb.y * 32 + lane] += h * h;
    h = fmaxf(sqrtf(ss2) - DELTA_VAR, 0.0f); myv[lb.z * 32 + lane] += h * h;
    h = fmaxf(sqrtf(ss3) - DELTA_VAR, 0.0f); myv[lb.w * 32 + lane] += h * h;
    __syncwarp();

    #pragma unroll
    for (int c = 0; c < CC; c++) {
        float vv = myv[c * 32 + lane];
        #pragma unroll
        for (int o = 16; o > 0; o >>= 1) vv += __shfl_xor_sync(0xffffffffu, vv, o);
        if (lane == 0) wpart[w][c] = vv;
    }
    __syncthreads();

    if (tid < CC) {
        float s = 0.0f;
        #pragma unroll
        for (int ww = 0; ww < 8; ww++) s += wpart[ww][tid];
        atomicAdd(&g_var[n][tid], s);
    }

    // ---- fused finalize: globally last pass2 block (across both launches) ----
    __threadfence();
    if (tid == 0) s_ticket = atomicAdd(&g_ticket, 1u);
    __syncthreads();
    if (s_ticket != P2_TOTAL - 1) return;
    __threadfence();   // make all blocks' g_var/g_sums/g_counts visible

    __shared__ float means_f[NB][CC][EE];   // 2 KB
    __shared__ float accf[NB][3];           // [n][0]=var, [1]=dist, [2]=reg

    if (tid < NB * 3) (&accf[0][0])[tid] = 0.0f;
    for (int i = tid; i < NB * CC * EE; i += P2_THREADS) {
        int nn = i >> 8, c = (i >> 4) & 15, e = i & 15;
        means_f[nn][c][e] = g_sums[nn][c][e] / g_counts[nn][c];
    }
    __syncthreads();

    if (tid < NB * CC) {   // variance + regularizer terms
        int nn = tid >> 4, c = tid & 15;
        atomicAdd(&accf[nn][0], g_var[nn][c] / g_counts[nn][c]);
        float s = 0.0f;
        #pragma unroll
        for (int e = 0; e < EE; e++) {
            float m = means_f[nn][c][e];
            s = fmaf(m, m, s);
        }
        atomicAdd(&accf[nn][2], sqrtf(s));
    }

    for (int i = tid; i < NB * CC * CC; i += P2_THREADS) {  // all-pairs repulsion
        int nn = i >> 8, a = (i >> 4) & 15, b = i & 15;
        float s = 0.0f;
        #pragma unroll
        for (int e = 0; e < EE; e++) {
            float d = means_f[nn][a][e] - means_f[nn][b][e];
            s = fmaf(d, d, s);
        }
        float dmat = sqrtf(s);
        float rep  = (a == b) ? 0.0f : (2.0f * DELTA_DIST);
        float hh   = fmaxf(rep - dmat, 0.0f);
        atomicAdd(&accf[nn][1], hh * hh);
    }
    __syncthreads();

    if (tid == 0) {
        float loss = 0.0f;
        #pragma unroll
        for (int nn = 0; nn < NB; nn++) {
            float var_term  = accf[nn][0] / (float)CC;
            float dist_term = accf[nn][1] / (float)(CC * (CC - 1));
            float reg_term  = accf[nn][2] / (float)CC;
            loss += var_term + dist_term + 0.001f * reg_term;
        }
        out[0] = loss / (float)NB;
        g_ticket = 0u;
    }
    __syncthreads();

    // re-zero scratch for the next (graph-replay) invocation
    {
        float* s = &g_sums[0][0][0];
        for (int i = tid; i < NB * CC * EE; i += P2_THREADS) s[i] = 0.0f;
        float* c = &g_counts[0][0];
        for (int i = tid; i < NB * CC; i += P2_THREADS) c[i] = 0.0f;
        float* vv = &g_var[0][0];
        for (int i = tid; i < NB * CC; i += P2_THREADS) vv[i] = 0.0f;
    }
}

// ---------------------------------------------------------------------------
// Batch-sequential launch order: pass1(n) primes L2 with batch n (71MB <
// 126MB L2), pass2(n) consumes it from L2 instead of DRAM.
// ---------------------------------------------------------------------------
extern "C" void kernel_launch(void* const* d_in, const int* in_sizes, int n_in,
                              void* d_out, int out_size) {
    const float* x = (const float*)d_in[0];   // [2,16,64,128,128] f32
    const int*   t = (const int*)d_in[1];     // [2,64,128,128]    i32
    float* out = (float*)d_out;

    pass1_kernel<<<P1_GX, 256>>>(x, t, 0);
    pass2_kernel<<<P2_GX, P2_THREADS>>>(x, t, out, 0);
    pass1_kernel<<<P1_GX, 256>>>(x, t, 1);
    pass2_kernel<<<P2_GX, P2_THREADS>>>(x, t, out, 1);
}

// round 11
// speedup vs baseline: 1.7390x; 1.7390x over previous
#include <cuda_runtime.h>
#include <cuda_bf16.h>
#include <math.h>

// Problem constants
#define NB 2
#define EE 16
#define CC 16
#define VV (64*128*128)              // 1,048,576 voxels per batch

#define CHUNK1 4096
#define P1_GX (VV / CHUNK1)          // 256 chunks
#define P1_ITERS (CHUNK1 / 128)      // 32 float4-iterations per lane

#define P2_THREADS 128
#define P2_GX (VV / (P2_THREADS*4))  // 2048 blocks in x (one float4-group per thread)
#define P2_TOTAL (P2_GX * NB)        // 4096 blocks total (ticket target)

#define DELTA_VAR 0.5f
#define DELTA_DIST 1.5f

// Scratch (device globals; zero-initialized at load; the fused finalize
// re-zeros them after consuming, so every call sees zeros -> deterministic).
__device__ float g_sums[NB][CC][EE];
__device__ float g_counts[NB][CC];
__device__ float g_var[NB][CC];
__device__ unsigned int g_ticket;

// ---------------------------------------------------------------------------
// Pass 1 (unchanged from measured 47us/3.1TB/s version): per-cluster sums +
// counts. 8 warps; warp w owns planes w and w+8 as two DISJOINT per-lane-
// column smem accumulators (bank==lane, conflict-free). Labels LDG'd as int4.
// Depth-2 software pipeline -> 6 LDG.128 in flight per warp.
// smem: 16KB A + 16KB B + 2KB C = 34KB static.
// ---------------------------------------------------------------------------
__global__ __launch_bounds__(256)
void pass1_kernel(const float* __restrict__ x, const int* __restrict__ t) {
    __shared__ float accA[8][CC * 32];   // 16 KB  (plane w)
    __shared__ float accB[8][CC * 32];   // 16 KB  (plane w+8)
    __shared__ float accC[CC * 32];      // 2 KB   (counts, warp 0)

    const int n    = blockIdx.y;
    const int base = blockIdx.x * CHUNK1;
    const int tid  = threadIdx.x;
    const int w    = tid >> 5;
    const int lane = tid & 31;

    for (int i = tid; i < 8 * CC * 32; i += 256) {
        (&accA[0][0])[i] = 0.0f;
        (&accB[0][0])[i] = 0.0f;
    }
    for (int i = tid; i < CC * 32; i += 256) accC[i] = 0.0f;
    __syncthreads();

    float* A = accA[w];
    float* B = accB[w];
    const float* xpA = x + ((size_t)n * EE + w    ) * VV + base;
    const float* xpB = x + ((size_t)n * EE + w + 8) * VV + base;
    const int*   tp  = t + (size_t)n * VV + base;

    // depth-2 pipeline: slots 0/1, 6 LDG.128 outstanding
    int i = lane * 4;
    float4 va0 = *(const float4*)(xpA + i);
    float4 vb0 = *(const float4*)(xpB + i);
    int4   lb0 = *(const int4*)(tp + i);
    float4 va1 = *(const float4*)(xpA + i + 128);
    float4 vb1 = *(const float4*)(xpB + i + 128);
    int4   lb1 = *(const int4*)(tp + i + 128);

    if (w == 0) {
        #pragma unroll
        for (int it = 0; it < P1_ITERS; it++) {
            float4 va = (it & 1) ? va1 : va0;
            float4 vb = (it & 1) ? vb1 : vb0;
            int4   lb = (it & 1) ? lb1 : lb0;
            if (it + 2 < P1_ITERS) {
                const int off = i + 256;
                if (it & 1) {
                    va1 = *(const float4*)(xpA + off);
                    vb1 = *(const float4*)(xpB + off);
                    lb1 = *(const int4*)(tp + off);
                } else {
                    va0 = *(const float4*)(xpA + off);
                    vb0 = *(const float4*)(xpB + off);
                    lb0 = *(const int4*)(tp + off);
                }
            }
            A[lb.x * 32 + lane] += va.x;  B[lb.x * 32 + lane] += vb.x;  accC[lb.x * 32 + lane] += 1.0f;
            A[lb.y * 32 + lane] += va.y;  B[lb.y * 32 + lane] += vb.y;  accC[lb.y * 32 + lane] += 1.0f;
            A[lb.z * 32 + lane] += va.z;  B[lb.z * 32 + lane] += vb.z;  accC[lb.z * 32 + lane] += 1.0f;
            A[lb.w * 32 + lane] += va.w;  B[lb.w * 32 + lane] += vb.w;  accC[lb.w * 32 + lane] += 1.0f;
            i += 128;
        }
    } else {
        #pragma unroll
        for (int it = 0; it < P1_ITERS; it++) {
            float4 va = (it & 1) ? va1 : va0;
            float4 vb = (it & 1) ? vb1 : vb0;
            int4   lb = (it & 1) ? lb1 : lb0;
            if (it + 2 < P1_ITERS) {
                const int off = i + 256;
                if (it & 1) {
                    va1 = *(const float4*)(xpA + off);
                    vb1 = *(const float4*)(xpB + off);
                    lb1 = *(const int4*)(tp + off);
                } else {
                    va0 = *(const float4*)(xpA + off);
                    vb0 = *(const float4*)(xpB + off);
                    lb0 = *(const int4*)(tp + off);
                }
            }
            A[lb.x * 32 + lane] += va.x;  B[lb.x * 32 + lane] += vb.x;
            A[lb.y * 32 + lane] += va.y;  B[lb.y * 32 + lane] += vb.y;
            A[lb.z * 32 + lane] += va.z;  B[lb.z * 32 + lane] += vb.z;
            A[lb.w * 32 + lane] += va.w;  B[lb.w * 32 + lane] += vb.w;
            i += 128;
        }
    }
    __syncwarp();

    #pragma unroll
    for (int c = 0; c < CC; c++) {
        float sA = A[c * 32 + lane];
        float sB = B[c * 32 + lane];
        #pragma unroll
        for (int o = 16; o > 0; o >>= 1) {
            sA += __shfl_xor_sync(0xffffffffu, sA, o);
            sB += __shfl_xor_sync(0xffffffffu, sB, o);
        }
        if (lane == 0) {
            atomicAdd(&g_sums[n][c][w],     sA);
            atomicAdd(&g_sums[n][c][w + 8], sB);
        }
        if (w == 0) {
            float sC = accC[c * 32 + lane];
            #pragma unroll
            for (int o = 16; o > 0; o >>= 1) sC += __shfl_xor_sync(0xffffffffu, sC, o);
            if (lane == 0) atomicAdd(&g_counts[n][c], sC);
        }
    }
}

// ---------------------------------------------------------------------------
// Pass 2: variance term, MLP-16 variant. 128-thread blocks (finer occupancy
// quantization); each thread owns one float4-group (4 voxels) and issues ALL
// 16 plane loads up front -> 16 independent LDG.128 in flight.
// Finalize FUSED into the globally last block via ticket.
// ---------------------------------------------------------------------------
__global__ __launch_bounds__(P2_THREADS)
void pass2_kernel(const float* __restrict__ x, const int* __restrict__ t,
                  float* __restrict__ out) {
    __shared__ float means_s[CC * 20];      // padded stride 20
    __shared__ float vacc[4][CC * 32];      // 8 KB (4 warps)
    __shared__ float wpart[4][CC];
    __shared__ unsigned int s_ticket;

    const int n    = blockIdx.y;
    const int tid  = threadIdx.x;
    const int w    = tid >> 5;
    const int lane = tid & 31;

    for (int i = tid; i < CC * EE; i += P2_THREADS) {
        int c = i >> 4, e = i & 15;
        means_s[c * 20 + e] = g_sums[n][c][e] / g_counts[n][c];
    }
    for (int i = tid; i < 4 * CC * 32; i += P2_THREADS) (&vacc[0][0])[i] = 0.0f;
    __syncthreads();

    // reversed bijective index -> 4 consecutive voxels, warp stays contiguous
    const int idx = (P2_GX * P2_THREADS - 1) - (blockIdx.x * P2_THREADS + tid);
    const int v   = idx * 4;

    const float* xb = x + (size_t)n * EE * VV;
    const int4 lb = *(const int4*)(t + (size_t)n * VV + v);

    // all 16 plane loads issued before any consumption -> MLP 16
    float4 xv[EE];
    #pragma unroll
    for (int e = 0; e < EE; e++)
        xv[e] = *(const float4*)(xb + (size_t)e * VV + v);

    float ss0 = 0.0f, ss1 = 0.0f, ss2 = 0.0f, ss3 = 0.0f;
    #pragma unroll
    for (int e = 0; e < EE; e++) {
        float d;
        d = xv[e].x - means_s[lb.x * 20 + e]; ss0 = fmaf(d, d, ss0);
        d = xv[e].y - means_s[lb.y * 20 + e]; ss1 = fmaf(d, d, ss1);
        d = xv[e].z - means_s[lb.z * 20 + e]; ss2 = fmaf(d, d, ss2);
        d = xv[e].w - means_s[lb.w * 20 + e]; ss3 = fmaf(d, d, ss3);
    }

    float* myv = vacc[w];
    float h;
    h = fmaxf(sqrtf(ss0) - DELTA_VAR, 0.0f); myv[lb.x * 32 + lane] += h * h;
    h = fmaxf(sqrtf(ss1) - DELTA_VAR, 0.0f); myv[lb.y * 32 + lane] += h * h;
    h = fmaxf(sqrtf(ss2) - DELTA_VAR, 0.0f); myv[lb.z * 32 + lane] += h * h;
    h = fmaxf(sqrtf(ss3) - DELTA_VAR, 0.0f); myv[lb.w * 32 + lane] += h * h;
    __syncwarp();

    #pragma unroll
    for (int c = 0; c < CC; c++) {
        float vv = myv[c * 32 + lane];
        #pragma unroll
        for (int o = 16; o > 0; o >>= 1) vv += __shfl_xor_sync(0xffffffffu, vv, o);
        if (lane == 0) wpart[w][c] = vv;
    }
    __syncthreads();

    if (tid < CC) {
        float s = 0.0f;
        #pragma unroll
        for (int ww = 0; ww < 4; ww++) s += wpart[ww][tid];
        atomicAdd(&g_var[n][tid], s);
    }

    // ---- fused finalize: globally last block does the tiny epilogue ----
    __threadfence();
    if (tid == 0) s_ticket = atomicAdd(&g_ticket, 1u);
    __syncthreads();
    if (s_ticket != P2_TOTAL - 1) return;
    __threadfence();   // make all blocks' g_var/g_sums/g_counts visible

    __shared__ float means_f[NB][CC][EE];   // 2 KB
    __shared__ float accf[NB][3];           // [n][0]=var, [1]=dist, [2]=reg

    if (tid < NB * 3) (&accf[0][0])[tid] = 0.0f;
    for (int i = tid; i < NB * CC * EE; i += P2_THREADS) {
        int nn = i >> 8, c = (i >> 4) & 15, e = i & 15;
        means_f[nn][c][e] = g_sums[nn][c][e] / g_counts[nn][c];
    }
    __syncthreads();

    if (tid < NB * CC) {   // variance + regularizer terms
        int nn = tid >> 4, c = tid & 15;
        atomicAdd(&accf[nn][0], g_var[nn][c] / g_counts[nn][c]);
        float s = 0.0f;
        #pragma unroll
        for (int e = 0; e < EE; e++) {
            float m = means_f[nn][c][e];
            s = fmaf(m, m, s);
        }
        atomicAdd(&accf[nn][2], sqrtf(s));
    }

    for (int i = tid; i < NB * CC * CC; i += P2_THREADS) {  // all-pairs repulsion
        int nn = i >> 8, a = (i >> 4) & 15, b = i & 15;
        float s = 0.0f;
        #pragma unroll
        for (int e = 0; e < EE; e++) {
            float d = means_f[nn][a][e] - means_f[nn][b][e];
            s = fmaf(d, d, s);
        }
        float dmat = sqrtf(s);
        float rep  = (a == b) ? 0.0f : (2.0f * DELTA_DIST);
        float hh   = fmaxf(rep - dmat, 0.0f);
        atomicAdd(&accf[nn][1], hh * hh);
    }
    __syncthreads();

    if (tid == 0) {
        float loss = 0.0f;
        #pragma unroll
        for (int nn = 0; nn < NB; nn++) {
            float var_term  = accf[nn][0] / (float)CC;
            float dist_term = accf[nn][1] / (float)(CC * (CC - 1));
            float reg_term  = accf[nn][2] / (float)CC;
            loss += var_term + dist_term + 0.001f * reg_term;
        }
        out[0] = loss / (float)NB;
        g_ticket = 0u;
    }
    __syncthreads();

    // re-zero scratch for the next (graph-replay) invocation
    {
        float* s = &g_sums[0][0][0];
        for (int i = tid; i < NB * CC * EE; i += P2_THREADS) s[i] = 0.0f;
        float* c = &g_counts[0][0];
        for (int i = tid; i < NB * CC; i += P2_THREADS) c[i] = 0.0f;
        float* vv = &g_var[0][0];
        for (int i = tid; i < NB * CC; i += P2_THREADS) vv[i] = 0.0f;
    }
}

// ---------------------------------------------------------------------------
extern "C" void kernel_launch(void* const* d_in, const int* in_sizes, int n_in,
                              void* d_out, int out_size) {
    const float* x = (const float*)d_in[0];   // [2,16,64,128,128] f32
    const int*   t = (const int*)d_in[1];     // [2,64,128,128]    i32
    float* out = (float*)d_out;

    pass1_kernel<<<dim3(P1_GX, NB), 256>>>(x, t);
    pass2_kernel<<<dim3(P2_GX, NB), P2_THREADS>>>(x, t, out);
}

// round 13
// speedup vs baseline: 1.8583x; 1.0686x over previous
#include <cuda_runtime.h>
#include <cuda_bf16.h>
#include <math.h>

// Problem constants
#define NB 2
#define EE 16
#define CC 16
#define VV (64*128*128)              // 1,048,576 voxels per batch

#define CHUNK1 8192
#define P1_GX (VV / CHUNK1)          // 128 chunks per batch
#define P1_ITERS (CHUNK1 / 128)      // 64 float4-iterations per lane
#define P1_TOTAL (P1_GX * NB)        // 256 pass1 blocks (means ticket)

#define P2_THREADS 256
#define P2_G 8                       // float4-groups per thread
#define P2_GX (VV / (P2_THREADS * 4 * P2_G))   // 128 blocks per batch
#define P2_TOTAL (P2_GX * NB)        // 256 blocks (finalize ticket)

#define DELTA_VAR 0.5f
#define DELTA_DIST 1.5f

// Scratch (device globals; zero-initialized at load; finalize re-zeros them
// after consuming, so every call sees zeros -> deterministic).
__device__ float g_sums[NB][CC][EE];
__device__ float g_counts[NB][CC];
__device__ float g_means[NB][CC][EE];    // written by pass1's last block
__device__ float g_var[NB][CC];
__device__ unsigned int g_ticket1;
__device__ unsigned int g_ticket2;

// ---------------------------------------------------------------------------
// Pass 1: per-cluster sums + counts (smem slot-split, depth-2 pipeline).
// 8 warps; warp w owns planes w and w+8 as two DISJOINT per-lane-column smem
// accumulators (bank==lane, conflict-free). Labels LDG'd directly as int4.
// Compact unroll-2 loop + peeled tail (small I$ footprint).
// Last block (ticket) computes g_means once -> no FDIV in pass2 prologues.
// smem: 16KB A + 16KB B + 2KB C = 34KB static.
// ---------------------------------------------------------------------------
__global__ __launch_bounds__(256)
void pass1_kernel(const float* __restrict__ x, const int* __restrict__ t) {
    __shared__ float accA[8][CC * 32];   // 16 KB  (plane w)
    __shared__ float accB[8][CC * 32];   // 16 KB  (plane w+8)
    __shared__ float accC[CC * 32];      // 2 KB   (counts, warp 0)
    __shared__ unsigned int s_t;

    const int n    = blockIdx.y;
    const int base = blockIdx.x * CHUNK1;
    const int tid  = threadIdx.x;
    const int w    = tid >> 5;
    const int lane = tid & 31;

    for (int i = tid; i < 8 * CC * 32; i += 256) {
        (&accA[0][0])[i] = 0.0f;
        (&accB[0][0])[i] = 0.0f;
    }
    for (int i = tid; i < CC * 32; i += 256) accC[i] = 0.0f;
    __syncthreads();

    float* A = accA[w];
    float* B = accB[w];
    const float* xpA = x + ((size_t)n * EE + w    ) * VV + base;
    const float* xpB = x + ((size_t)n * EE + w + 8) * VV + base;
    const int*   tp  = t + (size_t)n * VV + base;

    // depth-2 pipeline: slots 0/1, 6 LDG.128 outstanding
    int i = lane * 4;
    float4 va0 = *(const float4*)(xpA + i);
    float4 vb0 = *(const float4*)(xpB + i);
    int4   lb0 = *(const int4*)(tp + i);
    float4 va1 = *(const float4*)(xpA + i + 128);
    float4 vb1 = *(const float4*)(xpB + i + 128);
    int4   lb1 = *(const int4*)(tp + i + 128);

    if (w == 0) {
        #pragma unroll 2
        for (int it = 0; it < P1_ITERS - 2; it++) {
            float4 va, vb; int4 lb;
            if (it & 1) {
                va = va1; vb = vb1; lb = lb1;
                va1 = *(const float4*)(xpA + i + 256);
                vb1 = *(const float4*)(xpB + i + 256);
                lb1 = *(const int4*)(tp + i + 256);
            } else {
                va = va0; vb = vb0; lb = lb0;
                va0 = *(const float4*)(xpA + i + 256);
                vb0 = *(const float4*)(xpB + i + 256);
                lb0 = *(const int4*)(tp + i + 256);
            }
            A[lb.x * 32 + lane] += va.x;  B[lb.x * 32 + lane] += vb.x;  accC[lb.x * 32 + lane] += 1.0f;
            A[lb.y * 32 + lane] += va.y;  B[lb.y * 32 + lane] += vb.y;  accC[lb.y * 32 + lane] += 1.0f;
            A[lb.z * 32 + lane] += va.z;  B[lb.z * 32 + lane] += vb.z;  accC[lb.z * 32 + lane] += 1.0f;
            A[lb.w * 32 + lane] += va.w;  B[lb.w * 32 + lane] += vb.w;  accC[lb.w * 32 + lane] += 1.0f;
            i += 128;
        }
        // peeled tails: P1_ITERS-2 is even -> slot0 then slot1
        A[lb0.x * 32 + lane] += va0.x;  B[lb0.x * 32 + lane] += vb0.x;  accC[lb0.x * 32 + lane] += 1.0f;
        A[lb0.y * 32 + lane] += va0.y;  B[lb0.y * 32 + lane] += vb0.y;  accC[lb0.y * 32 + lane] += 1.0f;
        A[lb0.z * 32 + lane] += va0.z;  B[lb0.z * 32 + lane] += vb0.z;  accC[lb0.z * 32 + lane] += 1.0f;
        A[lb0.w * 32 + lane] += va0.w;  B[lb0.w * 32 + lane] += vb0.w;  accC[lb0.w * 32 + lane] += 1.0f;
        A[lb1.x * 32 + lane] += va1.x;  B[lb1.x * 32 + lane] += vb1.x;  accC[lb1.x * 32 + lane] += 1.0f;
        A[lb1.y * 32 + lane] += va1.y;  B[lb1.y * 32 + lane] += vb1.y;  accC[lb1.y * 32 + lane] += 1.0f;
        A[lb1.z * 32 + lane] += va1.z;  B[lb1.z * 32 + lane] += vb1.z;  accC[lb1.z * 32 + lane] += 1.0f;
        A[lb1.w * 32 + lane] += va1.w;  B[lb1.w * 32 + lane] += vb1.w;  accC[lb1.w * 32 + lane] += 1.0f;
    } else {
        #pragma unroll 2
        for (int it = 0; it < P1_ITERS - 2; it++) {
            float4 va, vb; int4 lb;
            if (it & 1) {
                va = va1; vb = vb1; lb = lb1;
                va1 = *(const float4*)(xpA + i + 256);
                vb1 = *(const float4*)(xpB + i + 256);
                lb1 = *(const int4*)(tp + i + 256);
            } else {
                va = va0; vb = vb0; lb = lb0;
                va0 = *(const float4*)(xpA + i + 256);
                vb0 = *(const float4*)(xpB + i + 256);
                lb0 = *(const int4*)(tp + i + 256);
            }
            A[lb.x * 32 + lane] += va.x;  B[lb.x * 32 + lane] += vb.x;
            A[lb.y * 32 + lane] += va.y;  B[lb.y * 32 + lane] += vb.y;
            A[lb.z * 32 + lane] += va.z;  B[lb.z * 32 + lane] += vb.z;
            A[lb.w * 32 + lane] += va.w;  B[lb.w * 32 + lane] += vb.w;
            i += 128;
        }
        A[lb0.x * 32 + lane] += va0.x;  B[lb0.x * 32 + lane] += vb0.x;
        A[lb0.y * 32 + lane] += va0.y;  B[lb0.y * 32 + lane] += vb0.y;
        A[lb0.z * 32 + lane] += va0.z;  B[lb0.z * 32 + lane] += vb0.z;
        A[lb0.w * 32 + lane] += va0.w;  B[lb0.w * 32 + lane] += vb0.w;
        A[lb1.x * 32 + lane] += va1.x;  B[lb1.x * 32 + lane] += vb1.x;
        A[lb1.y * 32 + lane] += va1.y;  B[lb1.y * 32 + lane] += vb1.y;
        A[lb1.z * 32 + lane] += va1.z;  B[lb1.z * 32 + lane] += vb1.z;
        A[lb1.w * 32 + lane] += va1.w;  B[lb1.w * 32 + lane] += vb1.w;
    }
    __syncwarp();

    #pragma unroll
    for (int c = 0; c < CC; c++) {
        float sA = A[c * 32 + lane];
        float sB = B[c * 32 + lane];
        #pragma unroll
        for (int o = 16; o > 0; o >>= 1) {
            sA += __shfl_xor_sync(0xffffffffu, sA, o);
            sB += __shfl_xor_sync(0xffffffffu, sB, o);
        }
        if (lane == 0) {
            atomicAdd(&g_sums[n][c][w],     sA);
            atomicAdd(&g_sums[n][c][w + 8], sB);
        }
        if (w == 0) {
            float sC = accC[c * 32 + lane];
            #pragma unroll
            for (int o = 16; o > 0; o >>= 1) sC += __shfl_xor_sync(0xffffffffu, sC, o);
            if (lane == 0) atomicAdd(&g_counts[n][c], sC);
        }
    }

    // ---- last pass1 block computes means once (no FDIV downstream) ----
    __threadfence();
    if (tid == 0) s_t = atomicAdd(&g_ticket1, 1u);
    __syncthreads();
    if (s_t != P1_TOTAL - 1) return;
    __threadfence();
    for (int i2 = tid; i2 < NB * CC * EE; i2 += 256) {
        int nn = i2 >> 8, c = (i2 >> 4) & 15, e = i2 & 15;
        g_means[nn][c][e] = g_sums[nn][c][e] / g_counts[nn][c];
    }
    if (tid == 0) g_ticket1 = 0u;
}

// ---------------------------------------------------------------------------
// Pass 2: variance term. FAT blocks: 256 threads x 8 groups/thread (8192
// voxels/block) so the prologue (means staging, vacc zero) and epilogue
// (reductions, ticket) are paid once per 8x payload. Inner loop = proven
// xv[8] two-batch load/consume; next group's labels prefetched.
// Finalize FUSED into the globally last block via ticket.
// ---------------------------------------------------------------------------
__global__ __launch_bounds__(P2_THREADS)
void pass2_kernel(const float* __restrict__ x, const int* __restrict__ t,
                  float* __restrict__ out) {
    __shared__ float means_s[CC * 20];      // padded stride 20
    __shared__ float vacc[8][CC * 32];      // 16 KB (8 warps)
    __shared__ float wpart[8][CC];
    __shared__ unsigned int s_ticket;

    const int n    = blockIdx.y;
    const int tid  = threadIdx.x;
    const int w    = tid >> 5;
    const int lane = tid & 31;

    if (tid < CC * EE) {
        int c = tid >> 4, e = tid & 15;
        means_s[c * 20 + e] = g_means[n][c][e];
    }
    for (int i = tid; i < 8 * CC * 32; i += P2_THREADS) (&vacc[0][0])[i] = 0.0f;
    __syncthreads();

    const float* xb = x + (size_t)n * EE * VV;
    const int*   tb = t + (size_t)n * VV;
    const int gbase = blockIdx.x * (P2_THREADS * P2_G);
    float* myv = vacc[w];

    int4 lb = *(const int4*)(tb + (size_t)(gbase + tid) * 4);

    #pragma unroll 2
    for (int g = 0; g < P2_G; g++) {
        const int v = (gbase + g * P2_THREADS + tid) * 4;
        int4 lbn;
        if (g + 1 < P2_G)
            lbn = *(const int4*)(tb + (size_t)(v + P2_THREADS * 4));

        float ss0 = 0.0f, ss1 = 0.0f, ss2 = 0.0f, ss3 = 0.0f;
        #pragma unroll
        for (int eo = 0; eo < EE; eo += 8) {
            float4 xv[8];
            #pragma unroll
            for (int e = 0; e < 8; e++)
                xv[e] = *(const float4*)(xb + (size_t)(eo + e) * VV + v);
            #pragma unroll
            for (int e = 0; e < 8; e++) {
                const int ee = eo + e;
                float d;
                d = xv[e].x - means_s[lb.x * 20 + ee]; ss0 = fmaf(d, d, ss0);
                d = xv[e].y - means_s[lb.y * 20 + ee]; ss1 = fmaf(d, d, ss1);
                d = xv[e].z - means_s[lb.z * 20 + ee]; ss2 = fmaf(d, d, ss2);
                d = xv[e].w - means_s[lb.w * 20 + ee]; ss3 = fmaf(d, d, ss3);
            }
        }

        float h;
        h = fmaxf(sqrtf(ss0) - DELTA_VAR, 0.0f); myv[lb.x * 32 + lane] += h * h;
        h = fmaxf(sqrtf(ss1) - DELTA_VAR, 0.0f); myv[lb.y * 32 + lane] += h * h;
        h = fmaxf(sqrtf(ss2) - DELTA_VAR, 0.0f); myv[lb.z * 32 + lane] += h * h;
        h = fmaxf(sqrtf(ss3) - DELTA_VAR, 0.0f); myv[lb.w * 32 + lane] += h * h;

        lb = lbn;
    }
    __syncwarp();

    #pragma unroll
    for (int c = 0; c < CC; c++) {
        float vv = myv[c * 32 + lane];
        #pragma unroll
        for (int o = 16; o > 0; o >>= 1) vv += __shfl_xor_sync(0xffffffffu, vv, o);
        if (lane == 0) wpart[w][c] = vv;
    }
    __syncthreads();

    if (tid < CC) {
        float s = 0.0f;
        #pragma unroll
        for (int ww = 0; ww < 8; ww++) s += wpart[ww][tid];
        atomicAdd(&g_var[n][tid], s);
    }

    // ---- fused finalize: globally last block does the tiny epilogue ----
    __threadfence();
    if (tid == 0) s_ticket = atomicAdd(&g_ticket2, 1u);
    __syncthreads();
    if (s_ticket != P2_TOTAL - 1) return;
    __threadfence();   // make all blocks' g_var visible

    __shared__ float accf[NB][3];           // [n][0]=var, [1]=dist, [2]=reg

    if (tid < NB * 3) (&accf[0][0])[tid] = 0.0f;
    __syncthreads();

    if (tid < NB * CC) {   // variance + regularizer terms
        int nn = tid >> 4, c = tid & 15;
        atomicAdd(&accf[nn][0], g_var[nn][c] / g_counts[nn][c]);
        float s = 0.0f;
        #pragma unroll
        for (int e = 0; e < EE; e++) {
            float m = g_means[nn][c][e];
            s = fmaf(m, m, s);
        }
        atomicAdd(&accf[nn][2], sqrtf(s));
    }

    for (int i = tid; i < NB * CC * CC; i += P2_THREADS) {  // all-pairs repulsion
        int nn = i >> 8, a = (i >> 4) & 15, b = i & 15;
        float s = 0.0f;
        #pragma unroll
        for (int e = 0; e < EE; e++) {
            float d = g_means[nn][a][e] - g_means[nn][b][e];
            s = fmaf(d, d, s);
        }
        float dmat = sqrtf(s);
        float rep  = (a == b) ? 0.0f : (2.0f * DELTA_DIST);
        float hh   = fmaxf(rep - dmat, 0.0f);
        atomicAdd(&accf[nn][1], hh * hh);
    }
    __syncthreads();

    if (tid == 0) {
        float loss = 0.0f;
        #pragma unroll
        for (int nn = 0; nn < NB; nn++) {
            float var_term  = accf[nn][0] / (float)CC;
            float dist_term = accf[nn][1] / (float)(CC * (CC - 1));
            float reg_term  = accf[nn][2] / (float)CC;
            loss += var_term + dist_term + 0.001f * reg_term;
        }
        out[0] = loss / (float)NB;
        g_ticket2 = 0u;
    }
    __syncthreads();

    // re-zero scratch for the next (graph-replay) invocation
    {
        float* s = &g_sums[0][0][0];
        for (int i = tid; i < NB * CC * EE; i += P2_THREADS) s[i] = 0.0f;
        float* c = &g_counts[0][0];
        for (int i = tid; i < NB * CC; i += P2_THREADS) c[i] = 0.0f;
        float* vv = &g_var[0][0];
        for (int i = tid; i < NB * CC; i += P2_THREADS) vv[i] = 0.0f;
    }
}

// ---------------------------------------------------------------------------
extern "C" void kernel_launch(void* const* d_in, const int* in_sizes, int n_in,
                              void* d_out, int out_size) {
    const float* x = (const float*)d_in[0];   // [2,16,64,128,128] f32
    const int*   t = (const int*)d_in[1];     // [2,64,128,128]    i32
    float* out = (float*)d_out;

    pass1_kernel<<<dim3(P1_GX, NB), 256>>>(x, t);
    pass2_kernel<<<dim3(P2_GX, NB), P2_THREADS>>>(x, t, out);
}

// round 16
// speedup vs baseline: 1.9327x; 1.0401x over previous
#include <cuda_runtime.h>
#include <cuda_bf16.h>
#include <math.h>

// Problem constants
#define NB 2
#define EE 16
#define CC 16
#define VV (64*128*128)              // 1,048,576 voxels per batch

#define CHUNK1 4096
#define P1_GX (VV / CHUNK1)          // 256 chunks per batch
#define P1_ITERS (CHUNK1 / 128)      // 32 float4-iterations per lane
#define P1_TOTAL (P1_GX * NB)        // 512 pass1 blocks (means ticket)

#define P2_THREADS 256
#define P2_G 4                       // float4-groups per thread
#define P2_GX (VV / (P2_THREADS * 4 * P2_G))   // 256 blocks per batch
#define P2_TOTAL (P2_GX * NB)        // 512 blocks (finalize ticket)

#define DELTA_VAR 0.5f
#define DELTA_DIST 1.5f

// Scratch (device globals; zero-initialized at load; finalize re-zeros them
// after consuming, so every call sees zeros -> deterministic).
__device__ float g_sums[NB][CC][EE];
__device__ float g_counts[NB][CC];
__device__ float g_means[NB][CC][EE];    // written by pass1's last block
__device__ float g_var[NB][CC];
__device__ unsigned int g_ticket1;
__device__ unsigned int g_ticket2;

// ---------------------------------------------------------------------------
// Pass 1: per-cluster sums + counts (smem slot-split, depth-2 pipeline).
// 512 blocks total -> all co-resident (smem 34KB -> 6/SM cap), single wave.
// 8 warps; warp w owns planes w and w+8 as two DISJOINT per-lane-column smem
// accumulators (bank==lane, conflict-free). Labels LDG'd directly as int4.
// Last block (ticket) computes g_means once -> no FDIV in pass2 prologues.
// ---------------------------------------------------------------------------
__global__ __launch_bounds__(256)
void pass1_kernel(const float* __restrict__ x, const int* __restrict__ t) {
    __shared__ float accA[8][CC * 32];   // 16 KB  (plane w)
    __shared__ float accB[8][CC * 32];   // 16 KB  (plane w+8)
    __shared__ float accC[CC * 32];      // 2 KB   (counts, warp 0)
    __shared__ unsigned int s_t;

    const int n    = blockIdx.y;
    const int base = blockIdx.x * CHUNK1;
    const int tid  = threadIdx.x;
    const int w    = tid >> 5;
    const int lane = tid & 31;

    for (int i = tid; i < 8 * CC * 32; i += 256) {
        (&accA[0][0])[i] = 0.0f;
        (&accB[0][0])[i] = 0.0f;
    }
    for (int i = tid; i < CC * 32; i += 256) accC[i] = 0.0f;
    __syncthreads();

    float* A = accA[w];
    float* B = accB[w];
    const float* xpA = x + ((size_t)n * EE + w    ) * VV + base;
    const float* xpB = x + ((size_t)n * EE + w + 8) * VV + base;
    const int*   tp  = t + (size_t)n * VV + base;

    // depth-2 pipeline: slots 0/1, 6 LDG.128 outstanding
    int i = lane * 4;
    float4 va0 = *(const float4*)(xpA + i);
    float4 vb0 = *(const float4*)(xpB + i);
    int4   lb0 = *(const int4*)(tp + i);
    float4 va1 = *(const float4*)(xpA + i + 128);
    float4 vb1 = *(const float4*)(xpB + i + 128);
    int4   lb1 = *(const int4*)(tp + i + 128);

    if (w == 0) {
        #pragma unroll 2
        for (int it = 0; it < P1_ITERS - 2; it++) {
            float4 va, vb; int4 lb;
            if (it & 1) {
                va = va1; vb = vb1; lb = lb1;
                va1 = *(const float4*)(xpA + i + 256);
                vb1 = *(const float4*)(xpB + i + 256);
                lb1 = *(const int4*)(tp + i + 256);
            } else {
                va = va0; vb = vb0; lb = lb0;
                va0 = *(const float4*)(xpA + i + 256);
                vb0 = *(const float4*)(xpB + i + 256);
                lb0 = *(const int4*)(tp + i + 256);
            }
            A[lb.x * 32 + lane] += va.x;  B[lb.x * 32 + lane] += vb.x;  accC[lb.x * 32 + lane] += 1.0f;
            A[lb.y * 32 + lane] += va.y;  B[lb.y * 32 + lane] += vb.y;  accC[lb.y * 32 + lane] += 1.0f;
            A[lb.z * 32 + lane] += va.z;  B[lb.z * 32 + lane] += vb.z;  accC[lb.z * 32 + lane] += 1.0f;
            A[lb.w * 32 + lane] += va.w;  B[lb.w * 32 + lane] += vb.w;  accC[lb.w * 32 + lane] += 1.0f;
            i += 128;
        }
        // peeled tails: P1_ITERS-2 is even -> slot0 then slot1
        A[lb0.x * 32 + lane] += va0.x;  B[lb0.x * 32 + lane] += vb0.x;  accC[lb0.x * 32 + lane] += 1.0f;
        A[lb0.y * 32 + lane] += va0.y;  B[lb0.y * 32 + lane] += vb0.y;  accC[lb0.y * 32 + lane] += 1.0f;
        A[lb0.z * 32 + lane] += va0.z;  B[lb0.z * 32 + lane] += vb0.z;  accC[lb0.z * 32 + lane] += 1.0f;
        A[lb0.w * 32 + lane] += va0.w;  B[lb0.w * 32 + lane] += vb0.w;  accC[lb0.w * 32 + lane] += 1.0f;
        A[lb1.x * 32 + lane] += va1.x;  B[lb1.x * 32 + lane] += vb1.x;  accC[lb1.x * 32 + lane] += 1.0f;
        A[lb1.y * 32 + lane] += va1.y;  B[lb1.y * 32 + lane] += vb1.y;  accC[lb1.y * 32 + lane] += 1.0f;
        A[lb1.z * 32 + lane] += va1.z;  B[lb1.z * 32 + lane] += vb1.z;  accC[lb1.z * 32 + lane] += 1.0f;
        A[lb1.w * 32 + lane] += va1.w;  B[lb1.w * 32 + lane] += vb1.w;  accC[lb1.w * 32 + lane] += 1.0f;
    } else {
        #pragma unroll 2
        for (int it = 0; it < P1_ITERS - 2; it++) {
            float4 va, vb; int4 lb;
            if (it & 1) {
                va = va1; vb = vb1; lb = lb1;
                va1 = *(const float4*)(xpA + i + 256);
                vb1 = *(const float4*)(xpB + i + 256);
                lb1 = *(const int4*)(tp + i + 256);
            } else {
                va = va0; vb = vb0; lb = lb0;
                va0 = *(const float4*)(xpA + i + 256);
                vb0 = *(const float4*)(xpB + i + 256);
                lb0 = *(const int4*)(tp + i + 256);
            }
            A[lb.x * 32 + lane] += va.x;  B[lb.x * 32 + lane] += vb.x;
            A[lb.y * 32 + lane] += va.y;  B[lb.y * 32 + lane] += vb.y;
            A[lb.z * 32 + lane] += va.z;  B[lb.z * 32 + lane] += vb.z;
            A[lb.w * 32 + lane] += va.w;  B[lb.w * 32 + lane] += vb.w;
            i += 128;
        }
        A[lb0.x * 32 + lane] += va0.x;  B[lb0.x * 32 + lane] += vb0.x;
        A[lb0.y * 32 + lane] += va0.y;  B[lb0.y * 32 + lane] += vb0.y;
        A[lb0.z * 32 + lane] += va0.z;  B[lb0.z * 32 + lane] += vb0.z;
        A[lb0.w * 32 + lane] += va0.w;  B[lb0.w * 32 + lane] += vb0.w;
        A[lb1.x * 32 + lane] += va1.x;  B[lb1.x * 32 + lane] += vb1.x;
        A[lb1.y * 32 + lane] += va1.y;  B[lb1.y * 32 + lane] += vb1.y;
        A[lb1.z * 32 + lane] += va1.z;  B[lb1.z * 32 + lane] += vb1.z;
        A[lb1.w * 32 + lane] += va1.w;  B[lb1.w * 32 + lane] += vb1.w;
    }
    __syncwarp();

    #pragma unroll
    for (int c = 0; c < CC; c++) {
        float sA = A[c * 32 + lane];
        float sB = B[c * 32 + lane];
        #pragma unroll
        for (int o = 16; o > 0; o >>= 1) {
            sA += __shfl_xor_sync(0xffffffffu, sA, o);
            sB += __shfl_xor_sync(0xffffffffu, sB, o);
        }
        if (lane == 0) {
            atomicAdd(&g_sums[n][c][w],     sA);
            atomicAdd(&g_sums[n][c][w + 8], sB);
        }
        if (w == 0) {
            float sC = accC[c * 32 + lane];
            #pragma unroll
            for (int o = 16; o > 0; o >>= 1) sC += __shfl_xor_sync(0xffffffffu, sC, o);
            if (lane == 0) atomicAdd(&g_counts[n][c], sC);
        }
    }

    // ---- last pass1 block computes means once (no FDIV downstream) ----
    __threadfence();
    if (tid == 0) s_t = atomicAdd(&g_ticket1, 1u);
    __syncthreads();
    if (s_t != P1_TOTAL - 1) return;
    __threadfence();
    for (int i2 = tid; i2 < NB * CC * EE; i2 += 256) {
        int nn = i2 >> 8, c = (i2 >> 4) & 15, e = i2 & 15;
        g_means[nn][c][e] = g_sums[nn][c][e] / g_counts[nn][c];
    }
    if (tid == 0) g_ticket1 = 0u;
}

// ---------------------------------------------------------------------------
// Pass 2: variance term. 256 threads x 4 groups/thread (4096 voxels/block),
// 512 blocks total -> ALL co-resident (regs<=62 -> 4 blocks/SM cap), single
// wave, ~28 warps/SM. Inner loop = proven xv[8] two-batch load/consume with
// next-group label prefetch. Finalize FUSED into the last block via ticket.
// ---------------------------------------------------------------------------
__global__ __launch_bounds__(P2_THREADS)
void pass2_kernel(const float* __restrict__ x, const int* __restrict__ t,
                  float* __restrict__ out) {
    __shared__ float means_s[CC * 20];      // padded stride 20
    __shared__ float vacc[8][CC * 32];      // 16 KB (8 warps)
    __shared__ float wpart[8][CC];
    __shared__ unsigned int s_ticket;

    const int n    = blockIdx.y;
    const int tid  = threadIdx.x;
    const int w    = tid >> 5;
    const int lane = tid & 31;

    if (tid < CC * EE) {
        int c = tid >> 4, e = tid & 15;
        means_s[c * 20 + e] = g_means[n][c][e];
    }
    for (int i = tid; i < 8 * CC * 32; i += P2_THREADS) (&vacc[0][0])[i] = 0.0f;
    __syncthreads();

    const float* xb = x + (size_t)n * EE * VV;
    const int*   tb = t + (size_t)n * VV;
    const int gbase = blockIdx.x * (P2_THREADS * P2_G);
    float* myv = vacc[w];

    int4 lb = *(const int4*)(tb + (size_t)(gbase + tid) * 4);

    #pragma unroll
    for (int g = 0; g < P2_G; g++) {
        const int v = (gbase + g * P2_THREADS + tid) * 4;
        int4 lbn;
        if (g + 1 < P2_G)
            lbn = *(const int4*)(tb + (size_t)(v + P2_THREADS * 4));

        float ss0 = 0.0f, ss1 = 0.0f, ss2 = 0.0f, ss3 = 0.0f;
        #pragma unroll
        for (int eo = 0; eo < EE; eo += 8) {
            float4 xv[8];
            #pragma unroll
            for (int e = 0; e < 8; e++)
                xv[e] = *(const float4*)(xb + (size_t)(eo + e) * VV + v);
            #pragma unroll
            for (int e = 0; e < 8; e++) {
                const int ee = eo + e;
                float d;
                d = xv[e].x - means_s[lb.x * 20 + ee]; ss0 = fmaf(d, d, ss0);
                d = xv[e].y - means_s[lb.y * 20 + ee]; ss1 = fmaf(d, d, ss1);
                d = xv[e].z - means_s[lb.z * 20 + ee]; ss2 = fmaf(d, d, ss2);
                d = xv[e].w - means_s[lb.w * 20 + ee]; ss3 = fmaf(d, d, ss3);
            }
        }

        float h;
        h = fmaxf(sqrtf(ss0) - DELTA_VAR, 0.0f); myv[lb.x * 32 + lane] += h * h;
        h = fmaxf(sqrtf(ss1) - DELTA_VAR, 0.0f); myv[lb.y * 32 + lane] += h * h;
        h = fmaxf(sqrtf(ss2) - DELTA_VAR, 0.0f); myv[lb.z * 32 + lane] += h * h;
        h = fmaxf(sqrtf(ss3) - DELTA_VAR, 0.0f); myv[lb.w * 32 + lane] += h * h;

        lb = lbn;
    }
    __syncwarp();

    #pragma unroll
    for (int c = 0; c < CC; c++) {
        float vv = myv[c * 32 + lane];
        #pragma unroll
        for (int o = 16; o > 0; o >>= 1) vv += __shfl_xor_sync(0xffffffffu, vv, o);
        if (lane == 0) wpart[w][c] = vv;
    }
    __syncthreads();

    if (tid < CC) {
        float s = 0.0f;
        #pragma unroll
        for (int ww = 0; ww < 8; ww++) s += wpart[ww][tid];
        atomicAdd(&g_var[n][tid], s);
    }

    // ---- fused finalize: globally last block does the tiny epilogue ----
    __threadfence();
    if (tid == 0) s_ticket = atomicAdd(&g_ticket2, 1u);
    __syncthreads();
    if (s_ticket != P2_TOTAL - 1) return;
    __threadfence();   // make all blocks' g_var visible

    __shared__ float accf[NB][3];           // [n][0]=var, [1]=dist, [2]=reg

    if (tid < NB * 3) (&accf[0][0])[tid] = 0.0f;
    __syncthreads();

    if (tid < NB * CC) {   // variance + regularizer terms
        int nn = tid >> 4, c = tid & 15;
        atomicAdd(&accf[nn][0], g_var[nn][c] / g_counts[nn][c]);
        float s = 0.0f;
        #pragma unroll
        for (int e = 0; e < EE; e++) {
            float m = g_means[nn][c][e];
            s = fmaf(m, m, s);
        }
        atomicAdd(&accf[nn][2], sqrtf(s));
    }

    for (int i = tid; i < NB * CC * CC; i += P2_THREADS) {  // all-pairs repulsion
        int nn = i >> 8, a = (i >> 4) & 15, b = i & 15;
        float s = 0.0f;
        #pragma unroll
        for (int e = 0; e < EE; e++) {
            float d = g_means[nn][a][e] - g_means[nn][b][e];
            s = fmaf(d, d, s);
        }
        float dmat = sqrtf(s);
        float rep  = (a == b) ? 0.0f : (2.0f * DELTA_DIST);
        float hh   = fmaxf(rep - dmat, 0.0f);
        atomicAdd(&accf[nn][1], hh * hh);
    }
    __syncthreads();

    if (tid == 0) {
        float loss = 0.0f;
        #pragma unroll
        for (int nn = 0; nn < NB; nn++) {
            float var_term  = accf[nn][0] / (float)CC;
            float dist_term = accf[nn][1] / (float)(CC * (CC - 1));
            float reg_term  = accf[nn][2] / (float)CC;
            loss += var_term + dist_term + 0.001f * reg_term;
        }
        out[0] = loss / (float)NB;
        g_ticket2 = 0u;
    }
    __syncthreads();

    // re-zero scratch for the next (graph-replay) invocation
    {
        float* s = &g_sums[0][0][0];
        for (int i = tid; i < NB * CC * EE; i += P2_THREADS) s[i] = 0.0f;
        float* c = &g_counts[0][0];
        for (int i = tid; i < NB * CC; i += P2_THREADS) c[i] = 0.0f;
        float* vv = &g_var[0][0];
        for (int i = tid; i < NB * CC; i += P2_THREADS) vv[i] = 0.0f;
    }
}

// ---------------------------------------------------------------------------
extern "C" void kernel_launch(void* const* d_in, const int* in_sizes, int n_in,
                              void* d_out, int out_size) {
    const float* x = (const float*)d_in[0];   // [2,16,64,128,128] f32
    const int*   t = (const int*)d_in[1];     // [2,64,128,128]    i32
    float* out = (float*)d_out;

    pass1_kernel<<<dim3(P1_GX, NB), 256>>>(x, t);
    pass2_kernel<<<dim3(P2_GX, NB), P2_THREADS>>>(x, t, out);
}